// round 16
// baseline (speedup 1.0000x reference)
#include <cuda_runtime.h>
#include <cuda_bf16.h>

#define HM 28
#define WM 28
#define ROWS_PER_BLOCK 8   // one warp per row, 256 threads

// ---------------------------------------------------------------------------
// One warp owns one output row. All per-row state (box rect, y-interp, n/y
// decode) is computed once per warp; the inner loop is pure STG.128 for the
// ~97% of rows outside the mask band. Grid-strides over 8-row groups because
// img_h/img_w live in device memory only.
//
// CONVERGED (5 consistent measurements: 83.9 / 84.1 / 83.8 / 83.9 / 83.9 us
// across two occupancy configs): DRAM ~70-72% (5.5-5.7 TB/s) is the HBM3e
// pure-write ceiling for this 524 MB store stream. issue (33%), occ (55%),
// alu (20%) all have slack; perturbing them (R7) did not move dur. Byte
// count is irreducible (harness poisons d_out; fp32 extent fixed).
// ---------------------------------------------------------------------------
__global__ __launch_bounds__(256)
void paste_rows_kernel(const float* __restrict__ masks,
                       const float* __restrict__ boxes,
                       const int* __restrict__ p_img_h,
                       const int* __restrict__ p_img_w,
                       const int* __restrict__ p_in_h,
                       const int* __restrict__ p_in_w,
                       float* __restrict__ out,
                       int out_elems) {
    const int img_h = *p_img_h;
    const int img_w = *p_img_w;
    const float sx = (float)img_w / (float)*p_in_w;
    const float sy = (float)img_h / (float)*p_in_h;

    const int warp = threadIdx.x >> 5;
    const int lane = threadIdx.x & 31;

    const int rows_total = out_elems / img_w;      // N * img_h
    const int groups = (rows_total + ROWS_PER_BLOCK - 1) / ROWS_PER_BLOCK;
    const bool vec4 = (img_w & 3) == 0;
    const int w4 = img_w >> 2;

    for (int g = blockIdx.x; g < groups; g += gridDim.x) {
        const int yg = g * ROWS_PER_BLOCK + warp;   // global row index
        if (yg >= rows_total) continue;
        const int n = yg / img_h;                   // image index (1 div / warp-row)
        const int y = yg - n * img_h;               // row within image

        // ---- per-warp uniform box state ----
        const float bx0 = __ldg(boxes + n * 4 + 0) * sx;
        const float by0 = __ldg(boxes + n * 4 + 1) * sy;
        const float bx1 = __ldg(boxes + n * 4 + 2) * sx;
        const float by1 = __ldg(boxes + n * 4 + 3) * sy;
        const float x0 = fminf(fmaxf(bx0, 0.f), (float)img_w);
        const float y0 = fminf(fmaxf(by0, 0.f), (float)img_h);
        const float x1 = fminf(fmaxf(bx1, 0.f), (float)img_w);
        const float y1 = fminf(fmaxf(by1, 0.f), (float)img_h);
        const float bw = x1 - x0;
        const float bh = y1 - y0;

        // Band test: row can only be non-zero if y+0.5 in (y0-ch/2, y1+ch/2).
        bool rowin = false;
        if (bw > 0.f && bh > 0.f) {
            const float ch = bh * (1.0f / HM);
            const float yc = (float)y + 0.5f;
            rowin = (yc > y0 - 0.5f * ch - 1.0f) && (yc < y1 + 0.5f * ch + 1.0f);
        }

        if (vec4) {
            float4* __restrict__ rowp = (float4*)(out + (size_t)yg * img_w);
            if (!rowin) {
                // pure store stream: the hot path (~97% of rows).
                // 4 independent STG.128 per iteration -> store queue stays full.
                const float4 z = make_float4(0.f, 0.f, 0.f, 0.f);
                int k = lane;
                for (; k + 96 < w4; k += 128) {
                    rowp[k]      = z;
                    rowp[k + 32] = z;
                    rowp[k + 64] = z;
                    rowp[k + 96] = z;
                }
                for (; k < w4; k += 32) rowp[k] = z;
            } else {
                // horizontal support rect + vertical interp (uniform per row)
                const float cw = bw * (1.0f / WM);
                const int xlo = max(0, (int)floorf(x0 - 0.5f * cw) - 1);
                const int xhi = min(img_w - 1, (int)ceilf(x1 + 0.5f * cw) + 1);
                const float gy = ((float)y + 0.5f - y0) / bh * 2.0f - 1.0f;
                const float py = (gy + 1.0f) * (HM * 0.5f) - 0.5f;
                const float fy = floorf(py);
                const int iy = (int)fy;
                const float wy1 = py - fy;
                const float wy0 = 1.0f - wy1;
                const bool v0ok = ((unsigned)iy < (unsigned)HM);
                const bool v1ok = ((unsigned)(iy + 1) < (unsigned)HM);
                const float* __restrict__ mrow = masks + n * (HM * WM);

                for (int k = lane; k < w4; k += 32) {
                    const int xb = k * 4;
                    float4 v = make_float4(0.f, 0.f, 0.f, 0.f);
                    if (xb + 3 >= xlo && xb <= xhi) {
                        float r[4];
                        #pragma unroll
                        for (int l = 0; l < 4; ++l) {
                            const int x = xb + l;
                            const float gx = ((float)x + 0.5f - x0) / bw * 2.0f - 1.0f;
                            const float px = (gx + 1.0f) * (WM * 0.5f) - 0.5f;
                            const float fx = floorf(px);
                            const int ix = (int)fx;
                            const float wx1 = px - fx;
                            const float wx0 = 1.0f - wx1;
                            const bool u0 = ((unsigned)ix < (unsigned)WM);
                            const bool u1 = ((unsigned)(ix + 1) < (unsigned)WM);
                            const float m00 = (v0ok && u0) ? __ldg(mrow + iy * WM + ix)           : 0.f;
                            const float m01 = (v0ok && u1) ? __ldg(mrow + iy * WM + ix + 1)       : 0.f;
                            const float m10 = (v1ok && u0) ? __ldg(mrow + (iy + 1) * WM + ix)     : 0.f;
                            const float m11 = (v1ok && u1) ? __ldg(mrow + (iy + 1) * WM + ix + 1) : 0.f;
                            r[l] = wy0 * (wx0 * m00 + wx1 * m01) +
                                   wy1 * (wx0 * m10 + wx1 * m11);
                        }
                        v = make_float4(r[0], r[1], r[2], r[3]);
                    }
                    rowp[k] = v;
                }
            }
        } else {
            // scalar fallback for img_w % 4 != 0 (not hit for 1280)
            float* __restrict__ rowp = out + (size_t)yg * img_w;
            if (!rowin) {
                for (int x = lane; x < img_w; x += 32) rowp[x] = 0.f;
            } else {
                const float cw = bw * (1.0f / WM);
                const int xlo = max(0, (int)floorf(x0 - 0.5f * cw) - 1);
                const int xhi = min(img_w - 1, (int)ceilf(x1 + 0.5f * cw) + 1);
                const float gy = ((float)y + 0.5f - y0) / bh * 2.0f - 1.0f;
                const float py = (gy + 1.0f) * (HM * 0.5f) - 0.5f;
                const float fy = floorf(py);
                const int iy = (int)fy;
                const float wy1 = py - fy;
                const float wy0 = 1.0f - wy1;
                const bool v0ok = ((unsigned)iy < (unsigned)HM);
                const bool v1ok = ((unsigned)(iy + 1) < (unsigned)HM);
                const float* __restrict__ mrow = masks + n * (HM * WM);
                for (int x = lane; x < img_w; x += 32) {
                    float r = 0.f;
                    if (x >= xlo && x <= xhi) {
                        const float gx = ((float)x + 0.5f - x0) / bw * 2.0f - 1.0f;
                        const float px = (gx + 1.0f) * (WM * 0.5f) - 0.5f;
                        const float fx = floorf(px);
                        const int ix = (int)fx;
                        const float wx1 = px - fx;
                        const float wx0 = 1.0f - wx1;
                        const bool u0 = ((unsigned)ix < (unsigned)WM);
                        const bool u1 = ((unsigned)(ix + 1) < (unsigned)WM);
                        const float m00 = (v0ok && u0) ? __ldg(mrow + iy * WM + ix)           : 0.f;
                        const float m01 = (v0ok && u1) ? __ldg(mrow + iy * WM + ix + 1)       : 0.f;
                        const float m10 = (v1ok && u0) ? __ldg(mrow + (iy + 1) * WM + ix)     : 0.f;
                        const float m11 = (v1ok && u1) ? __ldg(mrow + (iy + 1) * WM + ix + 1) : 0.f;
                        r = wy0 * (wx0 * m00 + wx1 * m01) + wy1 * (wx0 * m10 + wx1 * m11);
                    }
                    rowp[x] = r;
                }
            }
        }
    }
}

// ---------------------------------------------------------------------------
// Launch: single kernel, fixed grid (geometry only known on device).
// Graph-capturable, allocation-free, sync-free.
// ---------------------------------------------------------------------------
extern "C" void kernel_launch(void* const* d_in, const int* in_sizes, int n_in,
                              void* d_out, int out_size) {
    const float* masks = (const float*)d_in[0];
    const float* boxes = (const float*)d_in[1];
    const int* p_img_h = (const int*)d_in[2];
    const int* p_img_w = (const int*)d_in[3];
    const int* p_in_h  = (const int*)d_in[4];
    const int* p_in_w  = (const int*)d_in[5];
    float* out = (float*)d_out;

    // 1792 blocks x 256 threads; each block grid-strides over 8-row groups.
    paste_rows_kernel<<<1792, 256>>>(masks, boxes, p_img_h, p_img_w,
                                     p_in_h, p_in_w, out, out_size);
}

// round 17
// speedup vs baseline: 1.0038x; 1.0038x over previous
#include <cuda_runtime.h>
#include <cuda_bf16.h>

#define HM 28
#define WM 28
#define ROWS_PER_BLOCK 8   // one warp per row, 256 threads

// ---------------------------------------------------------------------------
// One warp owns one output row. All per-row state (box rect, y-interp, n/y
// decode) is computed once per warp; the inner loop is pure STG.128 for the
// ~97% of rows outside the mask band. Grid-strides over 8-row groups because
// img_h/img_w live in device memory only.
//
// CONVERGED (6 consistent measurements: 83.9 / 84.1 / 83.8 / 83.9 / 83.9 /
// 83.9 us across two occupancy configs): DRAM ~70-73% (5.5-5.8 TB/s) is the
// HBM3e pure-write ceiling for this 524 MB store stream. issue (33%),
// occ (55%), alu (20%) all have slack; perturbing them (R7) did not move
// dur. Byte count is irreducible (harness poisons d_out; fp32 extent fixed).
// ---------------------------------------------------------------------------
__global__ __launch_bounds__(256)
void paste_rows_kernel(const float* __restrict__ masks,
                       const float* __restrict__ boxes,
                       const int* __restrict__ p_img_h,
                       const int* __restrict__ p_img_w,
                       const int* __restrict__ p_in_h,
                       const int* __restrict__ p_in_w,
                       float* __restrict__ out,
                       int out_elems) {
    const int img_h = *p_img_h;
    const int img_w = *p_img_w;
    const float sx = (float)img_w / (float)*p_in_w;
    const float sy = (float)img_h / (float)*p_in_h;

    const int warp = threadIdx.x >> 5;
    const int lane = threadIdx.x & 31;

    const int rows_total = out_elems / img_w;      // N * img_h
    const int groups = (rows_total + ROWS_PER_BLOCK - 1) / ROWS_PER_BLOCK;
    const bool vec4 = (img_w & 3) == 0;
    const int w4 = img_w >> 2;

    for (int g = blockIdx.x; g < groups; g += gridDim.x) {
        const int yg = g * ROWS_PER_BLOCK + warp;   // global row index
        if (yg >= rows_total) continue;
        const int n = yg / img_h;                   // image index (1 div / warp-row)
        const int y = yg - n * img_h;               // row within image

        // ---- per-warp uniform box state ----
        const float bx0 = __ldg(boxes + n * 4 + 0) * sx;
        const float by0 = __ldg(boxes + n * 4 + 1) * sy;
        const float bx1 = __ldg(boxes + n * 4 + 2) * sx;
        const float by1 = __ldg(boxes + n * 4 + 3) * sy;
        const float x0 = fminf(fmaxf(bx0, 0.f), (float)img_w);
        const float y0 = fminf(fmaxf(by0, 0.f), (float)img_h);
        const float x1 = fminf(fmaxf(bx1, 0.f), (float)img_w);
        const float y1 = fminf(fmaxf(by1, 0.f), (float)img_h);
        const float bw = x1 - x0;
        const float bh = y1 - y0;

        // Band test: row can only be non-zero if y+0.5 in (y0-ch/2, y1+ch/2).
        bool rowin = false;
        if (bw > 0.f && bh > 0.f) {
            const float ch = bh * (1.0f / HM);
            const float yc = (float)y + 0.5f;
            rowin = (yc > y0 - 0.5f * ch - 1.0f) && (yc < y1 + 0.5f * ch + 1.0f);
        }

        if (vec4) {
            float4* __restrict__ rowp = (float4*)(out + (size_t)yg * img_w);
            if (!rowin) {
                // pure store stream: the hot path (~97% of rows).
                // 4 independent STG.128 per iteration -> store queue stays full.
                const float4 z = make_float4(0.f, 0.f, 0.f, 0.f);
                int k = lane;
                for (; k + 96 < w4; k += 128) {
                    rowp[k]      = z;
                    rowp[k + 32] = z;
                    rowp[k + 64] = z;
                    rowp[k + 96] = z;
                }
                for (; k < w4; k += 32) rowp[k] = z;
            } else {
                // horizontal support rect + vertical interp (uniform per row)
                const float cw = bw * (1.0f / WM);
                const int xlo = max(0, (int)floorf(x0 - 0.5f * cw) - 1);
                const int xhi = min(img_w - 1, (int)ceilf(x1 + 0.5f * cw) + 1);
                const float gy = ((float)y + 0.5f - y0) / bh * 2.0f - 1.0f;
                const float py = (gy + 1.0f) * (HM * 0.5f) - 0.5f;
                const float fy = floorf(py);
                const int iy = (int)fy;
                const float wy1 = py - fy;
                const float wy0 = 1.0f - wy1;
                const bool v0ok = ((unsigned)iy < (unsigned)HM);
                const bool v1ok = ((unsigned)(iy + 1) < (unsigned)HM);
                const float* __restrict__ mrow = masks + n * (HM * WM);

                for (int k = lane; k < w4; k += 32) {
                    const int xb = k * 4;
                    float4 v = make_float4(0.f, 0.f, 0.f, 0.f);
                    if (xb + 3 >= xlo && xb <= xhi) {
                        float r[4];
                        #pragma unroll
                        for (int l = 0; l < 4; ++l) {
                            const int x = xb + l;
                            const float gx = ((float)x + 0.5f - x0) / bw * 2.0f - 1.0f;
                            const float px = (gx + 1.0f) * (WM * 0.5f) - 0.5f;
                            const float fx = floorf(px);
                            const int ix = (int)fx;
                            const float wx1 = px - fx;
                            const float wx0 = 1.0f - wx1;
                            const bool u0 = ((unsigned)ix < (unsigned)WM);
                            const bool u1 = ((unsigned)(ix + 1) < (unsigned)WM);
                            const float m00 = (v0ok && u0) ? __ldg(mrow + iy * WM + ix)           : 0.f;
                            const float m01 = (v0ok && u1) ? __ldg(mrow + iy * WM + ix + 1)       : 0.f;
                            const float m10 = (v1ok && u0) ? __ldg(mrow + (iy + 1) * WM + ix)     : 0.f;
                            const float m11 = (v1ok && u1) ? __ldg(mrow + (iy + 1) * WM + ix + 1) : 0.f;
                            r[l] = wy0 * (wx0 * m00 + wx1 * m01) +
                                   wy1 * (wx0 * m10 + wx1 * m11);
                        }
                        v = make_float4(r[0], r[1], r[2], r[3]);
                    }
                    rowp[k] = v;
                }
            }
        } else {
            // scalar fallback for img_w % 4 != 0 (not hit for 1280)
            float* __restrict__ rowp = out + (size_t)yg * img_w;
            if (!rowin) {
                for (int x = lane; x < img_w; x += 32) rowp[x] = 0.f;
            } else {
                const float cw = bw * (1.0f / WM);
                const int xlo = max(0, (int)floorf(x0 - 0.5f * cw) - 1);
                const int xhi = min(img_w - 1, (int)ceilf(x1 + 0.5f * cw) + 1);
                const float gy = ((float)y + 0.5f - y0) / bh * 2.0f - 1.0f;
                const float py = (gy + 1.0f) * (HM * 0.5f) - 0.5f;
                const float fy = floorf(py);
                const int iy = (int)fy;
                const float wy1 = py - fy;
                const float wy0 = 1.0f - wy1;
                const bool v0ok = ((unsigned)iy < (unsigned)HM);
                const bool v1ok = ((unsigned)(iy + 1) < (unsigned)HM);
                const float* __restrict__ mrow = masks + n * (HM * WM);
                for (int x = lane; x < img_w; x += 32) {
                    float r = 0.f;
                    if (x >= xlo && x <= xhi) {
                        const float gx = ((float)x + 0.5f - x0) / bw * 2.0f - 1.0f;
                        const float px = (gx + 1.0f) * (WM * 0.5f) - 0.5f;
                        const float fx = floorf(px);
                        const int ix = (int)fx;
                        const float wx1 = px - fx;
                        const float wx0 = 1.0f - wx1;
                        const bool u0 = ((unsigned)ix < (unsigned)WM);
                        const bool u1 = ((unsigned)(ix + 1) < (unsigned)WM);
                        const float m00 = (v0ok && u0) ? __ldg(mrow + iy * WM + ix)           : 0.f;
                        const float m01 = (v0ok && u1) ? __ldg(mrow + iy * WM + ix + 1)       : 0.f;
                        const float m10 = (v1ok && u0) ? __ldg(mrow + (iy + 1) * WM + ix)     : 0.f;
                        const float m11 = (v1ok && u1) ? __ldg(mrow + (iy + 1) * WM + ix + 1) : 0.f;
                        r = wy0 * (wx0 * m00 + wx1 * m01) + wy1 * (wx0 * m10 + wx1 * m11);
                    }
                    rowp[x] = r;
                }
            }
        }
    }
}

// ---------------------------------------------------------------------------
// Launch: single kernel, fixed grid (geometry only known on device).
// Graph-capturable, allocation-free, sync-free.
// ---------------------------------------------------------------------------
extern "C" void kernel_launch(void* const* d_in, const int* in_sizes, int n_in,
                              void* d_out, int out_size) {
    const float* masks = (const float*)d_in[0];
    const float* boxes = (const float*)d_in[1];
    const int* p_img_h = (const int*)d_in[2];
    const int* p_img_w = (const int*)d_in[3];
    const int* p_in_h  = (const int*)d_in[4];
    const int* p_in_w  = (const int*)d_in[5];
    float* out = (float*)d_out;

    // 1792 blocks x 256 threads; each block grid-strides over 8-row groups.
    paste_rows_kernel<<<1792, 256>>>(masks, boxes, p_img_h, p_img_w,
                                     p_in_h, p_in_w, out, out_size);
}